// round 15
// baseline (speedup 1.0000x reference)
#include <cuda_runtime.h>
#include <cuda_fp16.h>
#include <cstdint>
#include <cstddef>

#define H 512
#define W 512
#define C 128
#define TI 16
#define TJ 16
// weights smem: [16 i][16 j][64 t] fp32, i-stride 1028 (== 4 mod 32):
// 4 row-lanes at bank groups {0,4,8,12}+c, chg lanes broadcast.
#define WISTRIDE 1028
#define W3_FLOATS (16 * WISTRIDE)          // 16448
// x halo (fp16): [8 chg][23 rows][24 colpad][4 ch]; 4 fp16 = 8 B = 2 u32.
// row stride 48 u32; chunk 1104 -> pad 1106 (== 18 mod 32).
#define XROWU 48
#define XCHUNK2 1106
#define XS_U32 (8 * XCHUNK2)               // 8848
#define SMEM_FLOATS (W3_FLOATS + XS_U32 + 529 + 256)
#define SMEM_BYTES (SMEM_FLOATS * 4)       // 104,324 B -> 2 CTAs/SM

typedef unsigned long long ull;

__device__ __forceinline__ ull pack2(float a, float b) {
    ull r; asm("mov.b64 %0, {%1, %2};" : "=l"(r) : "f"(a), "f"(b)); return r;
}
__device__ __forceinline__ void fma2(ull& d, ull a, ull b) {
    asm("fma.rn.f32x2 %0, %1, %2, %0;" : "+l"(d) : "l"(a), "l"(b));
}
__device__ __forceinline__ float2 unpack2(ull v) {
    float2 f; asm("mov.b64 {%0, %1}, %2;" : "=f"(f.x), "=f"(f.y) : "l"(v)); return f;
}
__device__ __forceinline__ void cp_async16(float* smem_dst, const float* gsrc) {
    uint32_t s = (uint32_t)__cvta_generic_to_shared(smem_dst);
    asm volatile("cp.async.cg.shared.global [%0], [%1], 16;\n"
                 :: "r"(s), "l"(gsrc));
}
__device__ __forceinline__ void cp_async4(float* smem_dst, const float* gsrc, bool pred) {
    uint32_t s = (uint32_t)__cvta_generic_to_shared(smem_dst);
    int sz = pred ? 4 : 0;
    asm volatile("cp.async.ca.shared.global [%0], [%1], 4, %2;\n"
                 :: "r"(s), "l"(gsrc), "r"(sz));
}
__device__ __forceinline__ void cp_commit() {
    asm volatile("cp.async.commit_group;\n" ::: "memory");
}
template <int N> __device__ __forceinline__ void cp_wait() {
    asm volatile("cp.async.wait_group %0;\n" :: "n"(N) : "memory");
}

// ---- stage one 32-channel x pass: batched LDG -> cvt fp16 -> STS ----
// 4232 items; per thread 16 items in 4 batches of 4 (deep LDG MLP) + tail.
__device__ __forceinline__ void stage_one(uint32_t* xs2, const float* __restrict__ gx,
                                          int bi, int bj, int cbase, int u) {
    int q = u & 7, pix = u >> 3;
    int hr = pix / 23, hc = pix - hr * 23;
    int gr = bi + hr - 3, gcl = bj + hc - 3;
    float4 v = make_float4(0.f, 0.f, 0.f, 0.f);
    if ((unsigned)gr < H && (unsigned)gcl < W)
        v = *(const float4*)(gx + (((size_t)gr * W + gcl) * C + cbase + q * 4));
    __half2 h0 = __float22half2_rn(make_float2(v.x, v.y));
    __half2 h1 = __float22half2_rn(make_float2(v.z, v.w));
    uint2 st;
    st.x = *(uint32_t*)&h0;
    st.y = *(uint32_t*)&h1;
    *(uint2*)(xs2 + q * XCHUNK2 + (hr * 24 + hc) * 2) = st;
}

__device__ __forceinline__ void stage_x(uint32_t* xs2, const float* __restrict__ gx,
                                        int bi, int bj, int pass, int tid) {
    const int cbase = pass * 32;
    #pragma unroll
    for (int b = 0; b < 4; ++b) {
        float4 v[4];
        // phase 1: 4 independent LDGs (or zero-fill)
        #pragma unroll
        for (int k = 0; k < 4; ++k) {
            int u = tid + (b * 4 + k) * 256;
            int q = u & 7, pix = u >> 3;
            int hr = pix / 23, hc = pix - hr * 23;
            int gr = bi + hr - 3, gcl = bj + hc - 3;
            v[k] = make_float4(0.f, 0.f, 0.f, 0.f);
            if ((unsigned)gr < H && (unsigned)gcl < W)
                v[k] = *(const float4*)(gx + (((size_t)gr * W + gcl) * C + cbase + q * 4));
        }
        // phase 2: cvt + STS
        #pragma unroll
        for (int k = 0; k < 4; ++k) {
            int u = tid + (b * 4 + k) * 256;
            int q = u & 7, pix = u >> 3;
            int hr = pix / 23, hc = pix - hr * 23;
            __half2 h0 = __float22half2_rn(make_float2(v[k].x, v[k].y));
            __half2 h1 = __float22half2_rn(make_float2(v[k].z, v[k].w));
            uint2 st;
            st.x = *(uint32_t*)&h0;
            st.y = *(uint32_t*)&h1;
            *(uint2*)(xs2 + q * XCHUNK2 + (hr * 24 + hc) * 2) = st;
        }
    }
    int u = tid + 4096;
    if (u < 529 * 8) stage_one(xs2, gx, bi, bj, cbase, u);
}

// ---- compute one pass: 1 row x 8 cols x 4 ch, software-pipelined rows ----
__device__ __forceinline__ void compute_pass(const uint32_t* __restrict__ xs2,
                                             const float* __restrict__ w3,
                                             const float* __restrict__ inv,
                                             float* __restrict__ gout,
                                             int bi, int bj, int cbase,
                                             int row, int j0, int chg) {
    ull acc[8][2];
    #pragma unroll
    for (int j = 0; j < 8; ++j) { acc[j][0] = 0ull; acc[j][1] = 0ull; }

    const uint32_t* xb   = xs2 + chg * XCHUNK2 + j0 * 2;
    const float*    wrow = w3 + row * WISTRIDE + j0 * 64;

    // prefetch first 8 raw positions of row 0
    uint2 raw[8];
    {
        const uint2* xp = (const uint2*)(xb + row * XROWU);
        #pragma unroll
        for (int t = 0; t < 8; ++t) raw[t] = xp[t];
    }

    #pragma unroll
    for (int p = 0; p < 8; ++p) {
        const uint2* xp = (const uint2*)(xb + (row + p) * XROWU);
        ull xf[15][2];
        // convert prefetched first-8 (loads long since landed)
        #pragma unroll
        for (int t = 0; t < 8; ++t) {
            float2 f01 = __half22float2(*(__half2*)&raw[t].x);
            float2 f23 = __half22float2(*(__half2*)&raw[t].y);
            xf[t][0] = pack2(f01.x, f01.y);
            xf[t][1] = pack2(f23.x, f23.y);
        }
        // load + convert remaining 7 of current row
        #pragma unroll
        for (int t = 8; t < 15; ++t) {
            uint2 h = xp[t];
            float2 f01 = __half22float2(*(__half2*)&h.x);
            float2 f23 = __half22float2(*(__half2*)&h.y);
            xf[t][0] = pack2(f01.x, f01.y);
            xf[t][1] = pack2(f23.x, f23.y);
        }
        // prefetch next row's first 8 raw BEFORE the fma block (latency
        // hides behind the ~1000-instr fma sequence below)
        if (p < 7) {
            const uint2* xn = (const uint2*)(xb + (row + p + 1) * XROWU);
            #pragma unroll
            for (int t = 0; t < 8; ++t) raw[t] = xn[t];
        }
        #pragma unroll
        for (int j = 0; j < 8; ++j) {
            #pragma unroll
            for (int qg = 0; qg < 2; ++qg) {
                float4 w4 = *(const float4*)(wrow + j * 64 + p * 8 + qg * 4);
                const int t0 = j + qg * 4;
                ull w0 = pack2(w4.x, w4.x);
                ull w1 = pack2(w4.y, w4.y);
                ull w2 = pack2(w4.z, w4.z);
                ull w3p = pack2(w4.w, w4.w);
                fma2(acc[j][0], xf[t0 + 0][0], w0);
                fma2(acc[j][1], xf[t0 + 0][1], w0);
                fma2(acc[j][0], xf[t0 + 1][0], w1);
                fma2(acc[j][1], xf[t0 + 1][1], w1);
                fma2(acc[j][0], xf[t0 + 2][0], w2);
                fma2(acc[j][1], xf[t0 + 2][1], w2);
                fma2(acc[j][0], xf[t0 + 3][0], w3p);
                fma2(acc[j][1], xf[t0 + 3][1], w3p);
            }
        }
    }

    // ---- normalize + store (8 chg lanes -> 128 B contiguous per (row,j)) ----
    #pragma unroll
    for (int j = 0; j < 8; ++j) {
        float s = inv[row * 16 + j0 + j];
        float2 a0 = unpack2(acc[j][0]);
        float2 a1 = unpack2(acc[j][1]);
        float4 v = make_float4(a0.x * s, a0.y * s, a1.x * s, a1.y * s);
        *(float4*)(gout + (((size_t)(bi + row) * W + (bj + j0 + j)) * C
                           + cbase + chg * 4)) = v;
    }
}

__global__ __launch_bounds__(256, 2) void cell_att_kernel(
    const float* __restrict__ gx,   // [H][W][C]
    const float* __restrict__ gw,   // [H][W][64]
    const float* __restrict__ gc,   // [H][W]
    float* __restrict__ gout)       // [H][W][C]
{
    extern __shared__ float smem[];
    float*    w3  = smem;                        // fp32 weights
    uint32_t* xs2 = (uint32_t*)(w3 + W3_FLOATS); // fp16 x halo
    float*    ch  = (float*)(xs2 + XS_U32);      // 23x23 cnts halo (fp32)
    float*    inv = ch + 529;                    // 256 per-pixel normalizers

    const int tid = threadIdx.x;
    const int chg = tid & 7;            // channel quad (4 ch)
    const int row = (tid >> 3) & 15;    // 0..15
    const int jg  = tid >> 7;           // 0 or 1
    const int j0  = jg * 8;
    const int bi = blockIdx.y * TI, bj = blockIdx.x * TJ;
    // CTA-parity pass staggering: even CTAs 0,1,2,3; odd CTAs 2,3,0,1.
    const int pswap = ((blockIdx.x + blockIdx.y) & 1) << 1;

    // ---- stage weights (cp.async, natural layout) + cnts halo ----
    #pragma unroll 8
    for (int u = tid; u < 256 * 16; u += 256) {
        int quad = u & 15, px = u >> 4;
        int il = px >> 4, jl = px & 15;
        const float* src = gw + ((size_t)(bi + il) * W + (bj + jl)) * 64 + quad * 4;
        cp_async16(w3 + il * WISTRIDE + jl * 64 + quad * 4, src);
    }
    for (int u = tid; u < 529; u += 256) {
        int hr = u / 23, hc = u - hr * 23;
        int gr = bi + hr - 3, gcl = bj + hc - 3;
        bool ok = ((unsigned)gr < H) && ((unsigned)gcl < W);
        const float* src = ok ? gc + (size_t)gr * W + gcl : gc;
        cp_async4(ch + u, src, ok);
    }
    cp_commit();

    // ---- stage x for first (staggered) pass ----
    stage_x(xs2, gx, bi, bj, 0 ^ pswap, tid);

    cp_wait<0>();
    __syncthreads();                    // w3, ch, xs2 all visible

    // ---- normalizer: inv = 1/(att(cnts)+1e-6), one pixel per thread ----
    {
        int il = tid >> 4, jl = tid & 15;
        const float* wpx = w3 + il * WISTRIDE + jl * 64;
        float s = 0.f;
        #pragma unroll
        for (int p = 0; p < 8; ++p)
            #pragma unroll
            for (int q = 0; q < 8; ++q)
                s += ch[(il + p) * 23 + (jl + q)] * wpx[p * 8 + q];
        inv[tid] = 1.0f / (s + 1e-6f);
    }
    __syncthreads();                    // inv visible

    compute_pass(xs2, w3, inv, gout, bi, bj, (0 ^ pswap) * 32, row, j0, chg);

    #pragma unroll 1
    for (int pass = 1; pass < 4; ++pass) {
        const int ap = pass ^ pswap;
        __syncthreads();                // everyone done reading xs2
        stage_x(xs2, gx, bi, bj, ap, tid);
        __syncthreads();                // new xs2 visible
        compute_pass(xs2, w3, inv, gout, bi, bj, ap * 32, row, j0, chg);
    }
}

extern "C" void kernel_launch(void* const* d_in, const int* in_sizes, int n_in,
                              void* d_out, int out_size) {
    const float* x0 = (const float*)d_in[0];
    const float* w  = (const float*)d_in[1];
    const float* c  = (const float*)d_in[2];
    float* out      = (float*)d_out;
    cudaFuncSetAttribute(cell_att_kernel,
                         cudaFuncAttributeMaxDynamicSharedMemorySize, SMEM_BYTES);
    dim3 grid(W / TJ, H / TI);
    cell_att_kernel<<<grid, 256, SMEM_BYTES>>>(x0, w, c, out);
}